// round 15
// baseline (speedup 1.0000x reference)
#include <cuda_runtime.h>
#include <cuda_fp16.h>
#include <math.h>

#define NU 50000
#define NI 100000
#define NN 150000
#define D  64
#define NINT 128
#define NE 3000000
#define NL 2
#define SCAN_TB 256
#define NBLK ((NN + SCAN_TB - 1) / SCAN_TB)   // 586

// alpha scale: dot_int/(127*127) -> alpha = (dot+1)/2 = dot_int*K + 0.5
#define KQ (0.5f / 16129.0f)

// ---------------- scratch (device globals) ----------------------------------
__device__ __align__(256) float d_embA[NN * D];
__device__ __align__(256) float d_embB[NN * D];
__device__ __align__(256) float d_gnn[NN * D];
__device__ __align__(256) float d_int[NN * D];
__device__ __align__(256) __half d_scaledH[NN * D];  // fp16(dis[n]*emb[n])
// packed per-node record, 256B = 16 chunks x 16B:
//   chunk q = { 4B int8 g[4q..4q+3], 4B int8 i[4q..4q+3], 8B fp16 emb[4q..4q+3] }
// double-buffered: emb part written by previous layer's adaptive epilogue.
__device__ __align__(256) uint4 d_packA[NN * 16];
__device__ __align__(256) uint4 d_packB[NN * 16];
__device__ __align__(256) float d_dis[NN];
__device__ __align__(256) int   d_cnt[NN];
__device__ __align__(256) int   d_rowptr[NN + 1];
__device__ __align__(256) int   d_fill[NN];
__device__ __align__(256) int   d_csr_t[NE];
__device__ __align__(256) int   d_blksum[NBLK];

__device__ __forceinline__ float2 u2f2(unsigned u) {
    return __half22float2(*(__half2*)&u);
}
__device__ __forceinline__ unsigned pack_q127(float a, float b, float c, float d, float s) {
    int b0 = max(-127, min(127, __float2int_rn(a * s)));
    int b1 = max(-127, min(127, __float2int_rn(b * s)));
    int b2 = max(-127, min(127, __float2int_rn(c * s)));
    int b3 = max(-127, min(127, __float2int_rn(d * s)));
    return (unsigned)(b0 & 0xFF) | ((unsigned)(b1 & 0xFF) << 8) |
           ((unsigned)(b2 & 0xFF) << 16) | ((unsigned)(b3 & 0xFF) << 24);
}

// ---------------------------------------------------------------------------
__global__ void k_init(const float* __restrict__ ue, const float* __restrict__ ie,
                       float* __restrict__ out) {
    int i = blockIdx.x * blockDim.x + threadIdx.x;
    const int n4  = NN * D / 4;
    const int nu4 = NU * D / 4;
    if (i >= n4) return;
    float4 v = (i < nu4) ? ((const float4*)ue)[i] : ((const float4*)ie)[i - nu4];
    ((float4*)d_embA)[i] = v;
    ((float4*)out)[i]    = v;
}

__global__ void k_cnt_zero() {
    int i = blockIdx.x * blockDim.x + threadIdx.x;
    if (i < NN) d_cnt[i] = 0;
}

__global__ void k_cnt(const int* __restrict__ h) {
    int e = blockIdx.x * blockDim.x + threadIdx.x;
    if (e < NE) atomicAdd(&d_cnt[h[e]], 1);
}

__global__ void k_blocksum() {
    __shared__ int sh[SCAN_TB];
    int i = blockIdx.x * SCAN_TB + threadIdx.x;
    int v = (i < NN) ? d_cnt[i] : 0;
    sh[threadIdx.x] = v;
    __syncthreads();
    for (int off = SCAN_TB / 2; off > 0; off >>= 1) {
        if (threadIdx.x < off) sh[threadIdx.x] += sh[threadIdx.x + off];
        __syncthreads();
    }
    if (threadIdx.x == 0) d_blksum[blockIdx.x] = sh[0];
}

__global__ void k_scanblk() {
    __shared__ int sh[1024];
    int tid = threadIdx.x;
    sh[tid] = (tid < NBLK) ? d_blksum[tid] : 0;
    __syncthreads();
    for (int off = 1; off < 1024; off <<= 1) {
        int v = (tid >= off) ? sh[tid - off] : 0;
        __syncthreads();
        sh[tid] += v;
        __syncthreads();
    }
    if (tid < NBLK) d_blksum[tid] = (tid > 0) ? sh[tid - 1] : 0;
    if (tid == 0) d_rowptr[NN] = sh[1023];
}

__global__ void k_rowptr() {
    __shared__ int sh[SCAN_TB];
    int i = blockIdx.x * SCAN_TB + threadIdx.x;
    int c = (i < NN) ? d_cnt[i] : 0;
    sh[threadIdx.x] = c;
    __syncthreads();
    for (int off = 1; off < SCAN_TB; off <<= 1) {
        int v = (threadIdx.x >= off) ? sh[threadIdx.x - off] : 0;
        __syncthreads();
        sh[threadIdx.x] += v;
        __syncthreads();
    }
    if (i < NN) {
        int excl = sh[threadIdx.x] - c + d_blksum[blockIdx.x];
        d_rowptr[i] = excl;
        d_dis[i]  = (c > 0) ? rsqrtf((float)c) : 0.0f;
        d_fill[i] = 0;
    }
}

__global__ void k_csr(const int* __restrict__ h, const int* __restrict__ t) {
    int e = blockIdx.x * blockDim.x + threadIdx.x;
    if (e >= NE) return;
    int hh = h[e];
    int pos = d_rowptr[hh] + atomicAdd(&d_fill[hh], 1);
    d_csr_t[pos] = t[e];
}

// layer-0 shadows: scaledH = fp16(dis*embA), packA emb-part = fp16(embA)
__global__ void k_scale0() {
    int i = blockIdx.x * blockDim.x + threadIdx.x;   // float4 (=4 dims) index
    const int n4 = NN * D / 4;
    if (i >= n4) return;
    float s = d_dis[i >> 4];
    float4 v = ((const float4*)d_embA)[i];
    __half2 h0 = __floats2half2_rn(v.x, v.y);
    __half2 h1 = __floats2half2_rn(v.z, v.w);
    uint2 ue_;
    ue_.x = *(unsigned*)&h0; ue_.y = *(unsigned*)&h1;
    // i = n*16 + q  -> emb part of chunk q at byte offset i*16 + 8
    *(uint2*)((char*)d_packA + (size_t)i * 16 + 8) = ue_;
    __half2 s0 = __floats2half2_rn(s * v.x, s * v.y);
    __half2 s1 = __floats2half2_rn(s * v.z, s * v.w);
    uint2 us_;
    us_.x = *(unsigned*)&s0; us_.y = *(unsigned*)&s1;
    ((uint2*)d_scaledH)[i] = us_;
}

// warp per node, 16 lanes/edge, 2 edges per half-iter (4 edges in flight).
// gnn[n] = dis[n] * sum_t scaledH[t]; writes f32 row + int8 g-part into pack.
__global__ void k_spmm_gnn(uint4* __restrict__ pack) {
    int n = (blockIdx.x * blockDim.x + threadIdx.x) >> 5;
    int lane = threadIdx.x & 31;
    if (n >= NN) return;
    int half = lane >> 4;
    int q    = lane & 15;
    float dh = d_dis[n];
    float4 a0 = make_float4(0.f, 0.f, 0.f, 0.f);
    float4 a1 = make_float4(0.f, 0.f, 0.f, 0.f);
    int b = d_rowptr[n], e = d_rowptr[n + 1];
    int i = b + half;
    for (; i + 2 < e; i += 4) {
        int t0 = __ldg(&d_csr_t[i]);
        int t1 = __ldg(&d_csr_t[i + 2]);
        uint2 r0 = __ldg((const uint2*)(d_scaledH + t0 * D) + q);
        uint2 r1 = __ldg((const uint2*)(d_scaledH + t1 * D) + q);
        float2 f;
        f = u2f2(r0.x); a0.x += f.x; a0.y += f.y;
        f = u2f2(r0.y); a0.z += f.x; a0.w += f.y;
        f = u2f2(r1.x); a1.x += f.x; a1.y += f.y;
        f = u2f2(r1.y); a1.z += f.x; a1.w += f.y;
    }
    for (; i < e; i += 2) {
        int t0 = __ldg(&d_csr_t[i]);
        uint2 r0 = __ldg((const uint2*)(d_scaledH + t0 * D) + q);
        float2 f;
        f = u2f2(r0.x); a0.x += f.x; a0.y += f.y;
        f = u2f2(r0.y); a0.z += f.x; a0.w += f.y;
    }
    a0.x = dh * (a0.x + a1.x); a0.y = dh * (a0.y + a1.y);
    a0.z = dh * (a0.z + a1.z); a0.w = dh * (a0.w + a1.w);
    a0.x += __shfl_xor_sync(0xffffffffu, a0.x, 16);
    a0.y += __shfl_xor_sync(0xffffffffu, a0.y, 16);
    a0.z += __shfl_xor_sync(0xffffffffu, a0.z, 16);
    a0.w += __shfl_xor_sync(0xffffffffu, a0.w, 16);
    float sg = a0.x * a0.x + a0.y * a0.y + a0.z * a0.z + a0.w * a0.w;
    #pragma unroll
    for (int o = 8; o >= 1; o >>= 1) sg += __shfl_xor_sync(0xffffffffu, sg, o);
    float s = 127.0f / fmaxf(sqrtf(sg), 1e-8f);
    if (half == 0) {
        ((float4*)(d_gnn + n * D))[q] = a0;
        unsigned p = pack_q127(a0.x, a0.y, a0.z, a0.w, s);
        *(unsigned*)((char*)pack + (size_t)n * 256 + 16 * q) = p;   // g-bytes
    }
}

// warp-per-row softmax-intent projection; writes f32 row + int8 i-part into pack.
__global__ void k_intent(const float* __restrict__ cur, uint4* __restrict__ pack,
                         const float* __restrict__ uW, const float* __restrict__ iW) {
    __shared__ float WT[NINT][D + 1];
    __shared__ float rowbuf[8][D];
    int wid = threadIdx.x >> 5, lane = threadIdx.x & 31;
    int row0 = blockIdx.x * 8;
    const float* W = (row0 < NU) ? uW : iW;
    for (int idx = threadIdx.x; idx < D * NINT; idx += blockDim.x) {
        int dd = idx / NINT, j = idx % NINT;
        WT[j][dd] = W[idx];
    }
    __syncthreads();
    int row = row0 + wid;
    if (row >= NN) return;
    const float* src = cur + row * D;
    rowbuf[wid][lane]      = src[lane];
    rowbuf[wid][lane + 32] = src[lane + 32];
    __syncwarp();

    float lg[4] = {0.f, 0.f, 0.f, 0.f};
    #pragma unroll
    for (int dd = 0; dd < D; dd++) {
        float rb = rowbuf[wid][dd];
        #pragma unroll
        for (int s = 0; s < 4; s++) lg[s] += rb * WT[s * 32 + lane][dd];
    }
    float m = fmaxf(fmaxf(lg[0], lg[1]), fmaxf(lg[2], lg[3]));
    #pragma unroll
    for (int o = 16; o >= 1; o >>= 1) m = fmaxf(m, __shfl_xor_sync(0xffffffffu, m, o));
    float p[4], ssum = 0.f;
    #pragma unroll
    for (int s = 0; s < 4; s++) { p[s] = expf(lg[s] - m); ssum += p[s]; }
    #pragma unroll
    for (int o = 16; o >= 1; o >>= 1) ssum += __shfl_xor_sync(0xffffffffu, ssum, o);
    float inv = 1.0f / ssum;
    #pragma unroll
    for (int s = 0; s < 4; s++) p[s] *= inv;

    float o0 = 0.f, o1 = 0.f;
    #pragma unroll
    for (int s = 0; s < 4; s++) {
        #pragma unroll
        for (int l = 0; l < 32; l++) {
            float pv = __shfl_sync(0xffffffffu, p[s], l);
            int j = s * 32 + l;
            o0 += pv * WT[j][lane];
            o1 += pv * WT[j][lane + 32];
        }
    }
    d_int[row * D + lane]      = o0;
    d_int[row * D + lane + 32] = o1;
    float si = o0 * o0 + o1 * o1;
    #pragma unroll
    for (int o = 16; o >= 1; o >>= 1) si += __shfl_xor_sync(0xffffffffu, si, o);
    float s = 127.0f / fmaxf(sqrtf(si), 1e-8f);
    // int8 i-part: dim d -> byte n*256 + 16*(d/4) + 4 + (d%4)
    int d0 = lane, d1 = lane + 32;
    int q0 = max(-127, min(127, __float2int_rn(o0 * s)));
    int q1 = max(-127, min(127, __float2int_rn(o1 * s)));
    char* pc = (char*)pack + (size_t)row * 256;
    pc[16 * (d0 >> 2) + 4 + (d0 & 3)] = (char)q0;
    pc[16 * (d1 >> 2) + 4 + (d1 & 3)] = (char)q1;
}

// fused adaptive pass, warp per node, 16 lanes/edge, unrolled 2x per half.
// Per edge-lane: ONE uint4 gather = int8 g + int8 i + fp16 emb chunk.
__global__ void k_adaptive(const float* __restrict__ cur,
                           const uint4* __restrict__ packCur,
                           float* __restrict__ newe,
                           uint4* __restrict__ packNxt,
                           float* __restrict__ out) {
    int n = (blockIdx.x * blockDim.x + threadIdx.x) >> 5;
    int lane = threadIdx.x & 31;
    if (n >= NN) return;
    int half = lane >> 4;
    int q    = lane & 15;
    unsigned hmask = half ? 0xFFFF0000u : 0x0000FFFFu;
    int b = d_rowptr[n], e = d_rowptr[n + 1];

    // h-side packed chunk: x = g-bytes, y = i-bytes
    uint4 hv = __ldg(packCur + n * 16 + q);

    float rsg = 0.f, rsi = 0.f;
    float4 accg = make_float4(0.f, 0.f, 0.f, 0.f);
    float4 acci = make_float4(0.f, 0.f, 0.f, 0.f);

    int i = b + half;
    for (; i + 2 < e; i += 4) {
        int t0 = __ldg(&d_csr_t[i]);
        int t1 = __ldg(&d_csr_t[i + 2]);
        uint4 v0 = __ldg(packCur + t0 * 16 + q);
        uint4 v1 = __ldg(packCur + t1 * 16 + q);

        int g0 = __dp4a((int)hv.x, (int)v0.x, 0);
        int i0 = __dp4a((int)hv.y, (int)v0.y, 0);
        int g1 = __dp4a((int)hv.x, (int)v1.x, 0);
        int i1 = __dp4a((int)hv.y, (int)v1.y, 0);

        #pragma unroll
        for (int o = 8; o >= 1; o >>= 1) {
            g0 += __shfl_xor_sync(hmask, g0, o);
            i0 += __shfl_xor_sync(hmask, i0, o);
            g1 += __shfl_xor_sync(hmask, g1, o);
            i1 += __shfl_xor_sync(hmask, i1, o);
        }
        float ag0 = fmaf((float)g0, KQ, 0.5f);
        float ai0 = fmaf((float)i0, KQ, 0.5f);
        float ag1 = fmaf((float)g1, KQ, 0.5f);
        float ai1 = fmaf((float)i1, KQ, 0.5f);
        rsg += ag0 + ag1;
        rsi += ai0 + ai1;
        float2 f0 = u2f2(v0.z), f1 = u2f2(v0.w);
        float2 f2 = u2f2(v1.z), f3 = u2f2(v1.w);
        accg.x += ag0 * f0.x + ag1 * f2.x;
        accg.y += ag0 * f0.y + ag1 * f2.y;
        accg.z += ag0 * f1.x + ag1 * f3.x;
        accg.w += ag0 * f1.y + ag1 * f3.y;
        acci.x += ai0 * f0.x + ai1 * f2.x;
        acci.y += ai0 * f0.y + ai1 * f2.y;
        acci.z += ai0 * f1.x + ai1 * f3.x;
        acci.w += ai0 * f1.y + ai1 * f3.y;
    }
    for (; i < e; i += 2) {
        int t0 = __ldg(&d_csr_t[i]);
        uint4 v0 = __ldg(packCur + t0 * 16 + q);
        int g0 = __dp4a((int)hv.x, (int)v0.x, 0);
        int i0 = __dp4a((int)hv.y, (int)v0.y, 0);
        #pragma unroll
        for (int o = 8; o >= 1; o >>= 1) {
            g0 += __shfl_xor_sync(hmask, g0, o);
            i0 += __shfl_xor_sync(hmask, i0, o);
        }
        float ag0 = fmaf((float)g0, KQ, 0.5f);
        float ai0 = fmaf((float)i0, KQ, 0.5f);
        rsg += ag0;
        rsi += ai0;
        float2 f0 = u2f2(v0.z), f1 = u2f2(v0.w);
        accg.x += ag0 * f0.x; accg.y += ag0 * f0.y;
        accg.z += ag0 * f1.x; accg.w += ag0 * f1.y;
        acci.x += ai0 * f0.x; acci.y += ai0 * f0.y;
        acci.z += ai0 * f1.x; acci.w += ai0 * f1.y;
    }

    // combine halves (warp reconverged)
    rsg += __shfl_xor_sync(0xffffffffu, rsg, 16);
    rsi += __shfl_xor_sync(0xffffffffu, rsi, 16);
    accg.x += __shfl_xor_sync(0xffffffffu, accg.x, 16);
    accg.y += __shfl_xor_sync(0xffffffffu, accg.y, 16);
    accg.z += __shfl_xor_sync(0xffffffffu, accg.z, 16);
    accg.w += __shfl_xor_sync(0xffffffffu, accg.w, 16);
    acci.x += __shfl_xor_sync(0xffffffffu, acci.x, 16);
    acci.y += __shfl_xor_sync(0xffffffffu, acci.y, 16);
    acci.z += __shfl_xor_sync(0xffffffffu, acci.z, 16);
    acci.w += __shfl_xor_sync(0xffffffffu, acci.w, 16);

    float dg = (rsg > 0.f) ? (1.0f / rsg) : 0.f;
    float di = (rsi > 0.f) ? (1.0f / rsi) : 0.f;

    if (half == 0) {
        float4 gh4 = __ldg((const float4*)(d_gnn + n * D) + q);
        float4 ih4 = __ldg((const float4*)(d_int + n * D) + q);
        float4 e0  = __ldg((const float4*)(cur   + n * D) + q);
        float4 nv;
        nv.x = gh4.x + ih4.x + dg * accg.x + di * acci.x + e0.x;
        nv.y = gh4.y + ih4.y + dg * accg.y + di * acci.y + e0.y;
        nv.z = gh4.z + ih4.z + dg * accg.z + di * acci.z + e0.z;
        nv.w = gh4.w + ih4.w + dg * accg.w + di * acci.w + e0.w;
        ((float4*)(newe + n * D))[q] = nv;
        float4 ov = ((float4*)(out + n * D))[q];
        ov.x += nv.x; ov.y += nv.y; ov.z += nv.z; ov.w += nv.w;
        ((float4*)(out + n * D))[q] = ov;
        // shadows for next layer: fp16 scaled + fp16 emb into packNxt
        float ds = d_dis[n];
        __half2 s0 = __floats2half2_rn(ds * nv.x, ds * nv.y);
        __half2 s1 = __floats2half2_rn(ds * nv.z, ds * nv.w);
        uint2 us_;
        us_.x = *(unsigned*)&s0; us_.y = *(unsigned*)&s1;
        ((uint2*)(d_scaledH + n * D))[q] = us_;
        __half2 h0 = __floats2half2_rn(nv.x, nv.y);
        __half2 h1 = __floats2half2_rn(nv.z, nv.w);
        uint2 ue_;
        ue_.x = *(unsigned*)&h0; ue_.y = *(unsigned*)&h1;
        *(uint2*)((char*)packNxt + (size_t)n * 256 + 16 * q + 8) = ue_;
    }
}

// ---------------------------------------------------------------------------
extern "C" void kernel_launch(void* const* d_in, const int* in_sizes, int n_in,
                              void* d_out, int out_size) {
    const float* ue = (const float*)d_in[0];
    const float* ie = (const float*)d_in[1];
    const float* uW = (const float*)d_in[2];
    const float* iW = (const float*)d_in[3];
    const int*   h  = (const int*)d_in[4];
    const int*   t  = (const int*)d_in[5];
    float* out = (float*)d_out;

    const int TB = 256;
    const int n4   = NN * D / 4;
    const int gN4  = (n4 + TB - 1) / TB;
    const int gNN  = (NN + TB - 1) / TB;
    const int gE   = (NE + TB - 1) / TB;
    const int gNW  = (NN * 32 + TB - 1) / TB;   // warp-per-node

    float *embA, *embB;
    uint4 *packA, *packB;
    cudaGetSymbolAddress((void**)&embA, d_embA);
    cudaGetSymbolAddress((void**)&embB, d_embB);
    cudaGetSymbolAddress((void**)&packA, d_packA);
    cudaGetSymbolAddress((void**)&packB, d_packB);

    k_init<<<gN4, TB>>>(ue, ie, out);
    k_cnt_zero<<<gNN, TB>>>();
    k_cnt<<<gE, TB>>>(h);
    k_blocksum<<<NBLK, SCAN_TB>>>();
    k_scanblk<<<1, 1024>>>();
    k_rowptr<<<NBLK, SCAN_TB>>>();
    k_csr<<<gE, TB>>>(h, t);
    k_scale0<<<gN4, TB>>>();

    float* cur = embA;  float* nxt = embB;
    uint4* pCur = packA; uint4* pNxt = packB;
    for (int layer = 0; layer < NL; layer++) {
        k_spmm_gnn<<<gNW, TB>>>(pCur);
        k_intent<<<NN / 8, TB>>>(cur, pCur, uW, iW);
        k_adaptive<<<gNW, TB>>>(cur, pCur, nxt, pNxt, out);
        float* tf = cur; cur = nxt; nxt = tf;
        uint4* tp = pCur; pCur = pNxt; pNxt = tp;
    }
}

// round 16
// speedup vs baseline: 1.0124x; 1.0124x over previous
#include <cuda_runtime.h>
#include <cuda_fp16.h>
#include <math.h>

#define NU 50000
#define NI 100000
#define NN 150000
#define D  64
#define NINT 128
#define NE 3000000
#define NL 2
#define SCAN_TB 256
#define NBLK ((NN + SCAN_TB - 1) / SCAN_TB)   // 586

// alpha scale: dot_int/(127*127) -> alpha = (dot+1)/2 = dot_int*K + 0.5
#define KQ (0.5f / 16129.0f)

// ---------------- scratch (device globals) ----------------------------------
__device__ __align__(256) float d_embA[NN * D];
__device__ __align__(256) float d_embB[NN * D];
__device__ __align__(256) float d_gnn[NN * D];
__device__ __align__(256) float d_int[NN * D];
__device__ __align__(256) __half d_scaledH[NN * D];  // fp16(dis[n]*emb[n])
__device__ __align__(256) __half d_embHA[NN * D];    // fp16 emb shadow (dbl-buffered)
__device__ __align__(256) __half d_embHB[NN * D];
// int8 packed normalized rows: 128B/node; chunk c (8B) = { g[4c..4c+3], i[4c..4c+3] }
__device__ __align__(256) char d_nrm8[NN * 2 * D];
__device__ __align__(256) float d_dis[NN];
__device__ __align__(256) int   d_cnt[NN];
__device__ __align__(256) int   d_rowptr[NN + 1];
__device__ __align__(256) int   d_fill[NN];
__device__ __align__(256) int   d_csr_t[NE];
__device__ __align__(256) int   d_blksum[NBLK];

__device__ __forceinline__ float2 u2f2(unsigned u) {
    return __half22float2(*(__half2*)&u);
}
__device__ __forceinline__ unsigned pack_q127(float a, float b, float c, float d, float s) {
    int b0 = max(-127, min(127, __float2int_rn(a * s)));
    int b1 = max(-127, min(127, __float2int_rn(b * s)));
    int b2 = max(-127, min(127, __float2int_rn(c * s)));
    int b3 = max(-127, min(127, __float2int_rn(d * s)));
    return (unsigned)(b0 & 0xFF) | ((unsigned)(b1 & 0xFF) << 8) |
           ((unsigned)(b2 & 0xFF) << 16) | ((unsigned)(b3 & 0xFF) << 24);
}

// ---------------------------------------------------------------------------
__global__ void k_init(const float* __restrict__ ue, const float* __restrict__ ie,
                       float* __restrict__ out) {
    int i = blockIdx.x * blockDim.x + threadIdx.x;
    const int n4  = NN * D / 4;
    const int nu4 = NU * D / 4;
    if (i >= n4) return;
    float4 v = (i < nu4) ? ((const float4*)ue)[i] : ((const float4*)ie)[i - nu4];
    ((float4*)d_embA)[i] = v;
    ((float4*)out)[i]    = v;
}

__global__ void k_cnt_zero() {
    int i = blockIdx.x * blockDim.x + threadIdx.x;
    if (i < NN) d_cnt[i] = 0;
}

__global__ void k_cnt(const int* __restrict__ h) {
    int e = blockIdx.x * blockDim.x + threadIdx.x;
    if (e < NE) atomicAdd(&d_cnt[h[e]], 1);
}

__global__ void k_blocksum() {
    __shared__ int sh[SCAN_TB];
    int i = blockIdx.x * SCAN_TB + threadIdx.x;
    int v = (i < NN) ? d_cnt[i] : 0;
    sh[threadIdx.x] = v;
    __syncthreads();
    for (int off = SCAN_TB / 2; off > 0; off >>= 1) {
        if (threadIdx.x < off) sh[threadIdx.x] += sh[threadIdx.x + off];
        __syncthreads();
    }
    if (threadIdx.x == 0) d_blksum[blockIdx.x] = sh[0];
}

__global__ void k_scanblk() {
    __shared__ int sh[1024];
    int tid = threadIdx.x;
    sh[tid] = (tid < NBLK) ? d_blksum[tid] : 0;
    __syncthreads();
    for (int off = 1; off < 1024; off <<= 1) {
        int v = (tid >= off) ? sh[tid - off] : 0;
        __syncthreads();
        sh[tid] += v;
        __syncthreads();
    }
    if (tid < NBLK) d_blksum[tid] = (tid > 0) ? sh[tid - 1] : 0;
    if (tid == 0) d_rowptr[NN] = sh[1023];
}

__global__ void k_rowptr() {
    __shared__ int sh[SCAN_TB];
    int i = blockIdx.x * SCAN_TB + threadIdx.x;
    int c = (i < NN) ? d_cnt[i] : 0;
    sh[threadIdx.x] = c;
    __syncthreads();
    for (int off = 1; off < SCAN_TB; off <<= 1) {
        int v = (threadIdx.x >= off) ? sh[threadIdx.x - off] : 0;
        __syncthreads();
        sh[threadIdx.x] += v;
        __syncthreads();
    }
    if (i < NN) {
        int excl = sh[threadIdx.x] - c + d_blksum[blockIdx.x];
        d_rowptr[i] = excl;
        d_dis[i]  = (c > 0) ? rsqrtf((float)c) : 0.0f;
        d_fill[i] = 0;
    }
}

__global__ void k_csr(const int* __restrict__ h, const int* __restrict__ t) {
    int e = blockIdx.x * blockDim.x + threadIdx.x;
    if (e >= NE) return;
    int hh = h[e];
    int pos = d_rowptr[hh] + atomicAdd(&d_fill[hh], 1);
    d_csr_t[pos] = t[e];
}

// scaledH = fp16(dis[n]*embA), embHA = fp16(embA)  (layer-0 shadows)
__global__ void k_scale0() {
    int i = blockIdx.x * blockDim.x + threadIdx.x;
    const int n4 = NN * D / 4;
    if (i >= n4) return;
    float s = d_dis[i >> 4];
    float4 v = ((const float4*)d_embA)[i];
    __half2 h0 = __floats2half2_rn(v.x, v.y);
    __half2 h1 = __floats2half2_rn(v.z, v.w);
    uint2 ue_;
    ue_.x = *(unsigned*)&h0; ue_.y = *(unsigned*)&h1;
    ((uint2*)d_embHA)[i] = ue_;
    __half2 s0 = __floats2half2_rn(s * v.x, s * v.y);
    __half2 s1 = __floats2half2_rn(s * v.z, s * v.w);
    uint2 us_;
    us_.x = *(unsigned*)&s0; us_.y = *(unsigned*)&s1;
    ((uint2*)d_scaledH)[i] = us_;
}

// warp per node, 16 lanes/edge, 2 edges per half-iter (4 edges in flight).
// gnn[n] = dis[n] * sum_t scaledH[t] ; writes f32 row + int8 normalized g-part.
__global__ void k_spmm_gnn() {
    int n = (blockIdx.x * blockDim.x + threadIdx.x) >> 5;
    int lane = threadIdx.x & 31;
    if (n >= NN) return;
    int half = lane >> 4;
    int q    = lane & 15;
    float dh = d_dis[n];
    float4 a0 = make_float4(0.f, 0.f, 0.f, 0.f);
    float4 a1 = make_float4(0.f, 0.f, 0.f, 0.f);
    int b = d_rowptr[n], e = d_rowptr[n + 1];
    int i = b + half;
    for (; i + 2 < e; i += 4) {
        int t0 = __ldg(&d_csr_t[i]);
        int t1 = __ldg(&d_csr_t[i + 2]);
        uint2 r0 = __ldg((const uint2*)(d_scaledH + t0 * D) + q);
        uint2 r1 = __ldg((const uint2*)(d_scaledH + t1 * D) + q);
        float2 f;
        f = u2f2(r0.x); a0.x += f.x; a0.y += f.y;
        f = u2f2(r0.y); a0.z += f.x; a0.w += f.y;
        f = u2f2(r1.x); a1.x += f.x; a1.y += f.y;
        f = u2f2(r1.y); a1.z += f.x; a1.w += f.y;
    }
    for (; i < e; i += 2) {
        int t0 = __ldg(&d_csr_t[i]);
        uint2 r0 = __ldg((const uint2*)(d_scaledH + t0 * D) + q);
        float2 f;
        f = u2f2(r0.x); a0.x += f.x; a0.y += f.y;
        f = u2f2(r0.y); a0.z += f.x; a0.w += f.y;
    }
    a0.x = dh * (a0.x + a1.x); a0.y = dh * (a0.y + a1.y);
    a0.z = dh * (a0.z + a1.z); a0.w = dh * (a0.w + a1.w);
    a0.x += __shfl_xor_sync(0xffffffffu, a0.x, 16);
    a0.y += __shfl_xor_sync(0xffffffffu, a0.y, 16);
    a0.z += __shfl_xor_sync(0xffffffffu, a0.z, 16);
    a0.w += __shfl_xor_sync(0xffffffffu, a0.w, 16);
    float sg = a0.x * a0.x + a0.y * a0.y + a0.z * a0.z + a0.w * a0.w;
    #pragma unroll
    for (int o = 8; o >= 1; o >>= 1) sg += __shfl_xor_sync(0xffffffffu, sg, o);
    float s = 127.0f / fmaxf(sqrtf(sg), 1e-8f);
    if (half == 0) {
        ((float4*)(d_gnn + n * D))[q] = a0;
        unsigned p = pack_q127(a0.x, a0.y, a0.z, a0.w, s);
        *(unsigned*)(d_nrm8 + n * 2 * D + 8 * q) = p;
    }
}

// warp-per-row softmax-intent projection; writes f32 row + int8 normalized i-part.
__global__ void k_intent(const float* __restrict__ cur,
                         const float* __restrict__ uW, const float* __restrict__ iW) {
    __shared__ float WT[NINT][D + 1];
    __shared__ float rowbuf[8][D];
    int wid = threadIdx.x >> 5, lane = threadIdx.x & 31;
    int row0 = blockIdx.x * 8;
    const float* W = (row0 < NU) ? uW : iW;
    for (int idx = threadIdx.x; idx < D * NINT; idx += blockDim.x) {
        int dd = idx / NINT, j = idx % NINT;
        WT[j][dd] = W[idx];
    }
    __syncthreads();
    int row = row0 + wid;
    if (row >= NN) return;
    const float* src = cur + row * D;
    rowbuf[wid][lane]      = src[lane];
    rowbuf[wid][lane + 32] = src[lane + 32];
    __syncwarp();

    float lg[4] = {0.f, 0.f, 0.f, 0.f};
    #pragma unroll
    for (int dd = 0; dd < D; dd++) {
        float rb = rowbuf[wid][dd];
        #pragma unroll
        for (int s = 0; s < 4; s++) lg[s] += rb * WT[s * 32 + lane][dd];
    }
    float m = fmaxf(fmaxf(lg[0], lg[1]), fmaxf(lg[2], lg[3]));
    #pragma unroll
    for (int o = 16; o >= 1; o >>= 1) m = fmaxf(m, __shfl_xor_sync(0xffffffffu, m, o));
    float p[4], ssum = 0.f;
    #pragma unroll
    for (int s = 0; s < 4; s++) { p[s] = expf(lg[s] - m); ssum += p[s]; }
    #pragma unroll
    for (int o = 16; o >= 1; o >>= 1) ssum += __shfl_xor_sync(0xffffffffu, ssum, o);
    float inv = 1.0f / ssum;
    #pragma unroll
    for (int s = 0; s < 4; s++) p[s] *= inv;

    float o0 = 0.f, o1 = 0.f;
    #pragma unroll
    for (int s = 0; s < 4; s++) {
        #pragma unroll
        for (int l = 0; l < 32; l++) {
            float pv = __shfl_sync(0xffffffffu, p[s], l);
            int j = s * 32 + l;
            o0 += pv * WT[j][lane];
            o1 += pv * WT[j][lane + 32];
        }
    }
    d_int[row * D + lane]      = o0;
    d_int[row * D + lane + 32] = o1;
    float si = o0 * o0 + o1 * o1;
    #pragma unroll
    for (int o = 16; o >= 1; o >>= 1) si += __shfl_xor_sync(0xffffffffu, si, o);
    float s = 127.0f / fmaxf(sqrtf(si), 1e-8f);
    // int8 i-part: dim d -> byte n*128 + 8*(d/4) + 4 + (d%4)
    int d0 = lane, d1 = lane + 32;
    int q0 = max(-127, min(127, __float2int_rn(o0 * s)));
    int q1 = max(-127, min(127, __float2int_rn(o1 * s)));
    d_nrm8[row * 2 * D + 8 * (d0 >> 2) + 4 + (d0 & 3)] = (char)q0;
    d_nrm8[row * 2 * D + 8 * (d1 >> 2) + 4 + (d1 & 3)] = (char)q1;
}

// fused adaptive pass, warp per node, QUARTER-warp per edge (8 lanes), 4 edges
// in flight per warp-instruction. Per edge-lane: ONE uint4 nrm8 (both dots via
// 2x dp4a each) + ONE uint4 fp16 emb (8 dims). Quarter-scoped in-loop shuffles.
__global__ void k_adaptive(const float* __restrict__ cur,
                           const __half* __restrict__ curH,
                           float* __restrict__ newe,
                           __half* __restrict__ nxtH,
                           float* __restrict__ out) {
    int n = (blockIdx.x * blockDim.x + threadIdx.x) >> 5;
    int lane = threadIdx.x & 31;
    if (n >= NN) return;
    int sub = lane >> 3;        // which of 4 concurrent edges
    int q8  = lane & 7;         // 16B chunk within row (8 dims)
    unsigned qmask = 0xFFu << (8 * sub);
    int b = d_rowptr[n], e = d_rowptr[n + 1];

    // h-side nrm8 chunk: covers dims 8*q8 .. 8*q8+7
    //   x = g[0..3], y = i[0..3], z = g[4..7], w = i[4..7] (of this chunk)
    uint4 hv = __ldg((const uint4*)(d_nrm8 + n * 2 * D) + q8);

    float rsg = 0.f, rsi = 0.f;
    float accg[8] = {0.f, 0.f, 0.f, 0.f, 0.f, 0.f, 0.f, 0.f};
    float acci[8] = {0.f, 0.f, 0.f, 0.f, 0.f, 0.f, 0.f, 0.f};

    for (int i = b + sub; i < e; i += 4) {
        int t0 = __ldg(&d_csr_t[i]);
        uint4 v  = __ldg((const uint4*)(d_nrm8 + t0 * 2 * D) + q8);
        uint4 em = __ldg((const uint4*)(curH + t0 * D) + q8);

        int g = __dp4a((int)hv.x, (int)v.x, 0);
        g     = __dp4a((int)hv.z, (int)v.z, g);
        int ii = __dp4a((int)hv.y, (int)v.y, 0);
        ii     = __dp4a((int)hv.w, (int)v.w, ii);
        #pragma unroll
        for (int o = 4; o >= 1; o >>= 1) {
            g  += __shfl_xor_sync(qmask, g, o);
            ii += __shfl_xor_sync(qmask, ii, o);
        }
        float ag = fmaf((float)g,  KQ, 0.5f);
        float ai = fmaf((float)ii, KQ, 0.5f);
        rsg += ag;
        rsi += ai;
        float2 f0 = u2f2(em.x), f1 = u2f2(em.y), f2 = u2f2(em.z), f3 = u2f2(em.w);
        accg[0] += ag * f0.x; accg[1] += ag * f0.y;
        accg[2] += ag * f1.x; accg[3] += ag * f1.y;
        accg[4] += ag * f2.x; accg[5] += ag * f2.y;
        accg[6] += ag * f3.x; accg[7] += ag * f3.y;
        acci[0] += ai * f0.x; acci[1] += ai * f0.y;
        acci[2] += ai * f1.x; acci[3] += ai * f1.y;
        acci[4] += ai * f2.x; acci[5] += ai * f2.y;
        acci[6] += ai * f3.x; acci[7] += ai * f3.y;
    }

    // combine the 4 quarters (warp reconverged; lanes with same q8 share dims)
    rsg += __shfl_xor_sync(0xffffffffu, rsg, 8);
    rsg += __shfl_xor_sync(0xffffffffu, rsg, 16);
    rsi += __shfl_xor_sync(0xffffffffu, rsi, 8);
    rsi += __shfl_xor_sync(0xffffffffu, rsi, 16);
    #pragma unroll
    for (int k = 0; k < 8; k++) {
        accg[k] += __shfl_xor_sync(0xffffffffu, accg[k], 8);
        accg[k] += __shfl_xor_sync(0xffffffffu, accg[k], 16);
        acci[k] += __shfl_xor_sync(0xffffffffu, acci[k], 8);
        acci[k] += __shfl_xor_sync(0xffffffffu, acci[k], 16);
    }

    float dg = (rsg > 0.f) ? (1.0f / rsg) : 0.f;
    float di = (rsi > 0.f) ? (1.0f / rsi) : 0.f;

    if (sub == 0) {   // lanes 0..7 each own dims 8*q8 .. 8*q8+7
        const float4* gp = (const float4*)(d_gnn + n * D) + 2 * q8;
        const float4* ip = (const float4*)(d_int + n * D) + 2 * q8;
        const float4* ep = (const float4*)(cur   + n * D) + 2 * q8;
        float4 nv0, nv1;
        {
            float4 gh = __ldg(gp), ih = __ldg(ip), e0 = __ldg(ep);
            nv0.x = gh.x + ih.x + dg * accg[0] + di * acci[0] + e0.x;
            nv0.y = gh.y + ih.y + dg * accg[1] + di * acci[1] + e0.y;
            nv0.z = gh.z + ih.z + dg * accg[2] + di * acci[2] + e0.z;
            nv0.w = gh.w + ih.w + dg * accg[3] + di * acci[3] + e0.w;
        }
        {
            float4 gh = __ldg(gp + 1), ih = __ldg(ip + 1), e0 = __ldg(ep + 1);
            nv1.x = gh.x + ih.x + dg * accg[4] + di * acci[4] + e0.x;
            nv1.y = gh.y + ih.y + dg * accg[5] + di * acci[5] + e0.y;
            nv1.z = gh.z + ih.z + dg * accg[6] + di * acci[6] + e0.z;
            nv1.w = gh.w + ih.w + dg * accg[7] + di * acci[7] + e0.w;
        }
        ((float4*)(newe + n * D))[2 * q8]     = nv0;
        ((float4*)(newe + n * D))[2 * q8 + 1] = nv1;
        float4 ov0 = ((float4*)(out + n * D))[2 * q8];
        float4 ov1 = ((float4*)(out + n * D))[2 * q8 + 1];
        ov0.x += nv0.x; ov0.y += nv0.y; ov0.z += nv0.z; ov0.w += nv0.w;
        ov1.x += nv1.x; ov1.y += nv1.y; ov1.z += nv1.z; ov1.w += nv1.w;
        ((float4*)(out + n * D))[2 * q8]     = ov0;
        ((float4*)(out + n * D))[2 * q8 + 1] = ov1;
        // shadows for next layer: fp16 scaled + fp16 emb (OTHER buffer)
        float ds = d_dis[n];
        __half2 s0 = __floats2half2_rn(ds * nv0.x, ds * nv0.y);
        __half2 s1 = __floats2half2_rn(ds * nv0.z, ds * nv0.w);
        __half2 s2 = __floats2half2_rn(ds * nv1.x, ds * nv1.y);
        __half2 s3 = __floats2half2_rn(ds * nv1.z, ds * nv1.w);
        uint4 us_;
        us_.x = *(unsigned*)&s0; us_.y = *(unsigned*)&s1;
        us_.z = *(unsigned*)&s2; us_.w = *(unsigned*)&s3;
        ((uint4*)(d_scaledH + n * D))[q8] = us_;
        __half2 h0 = __floats2half2_rn(nv0.x, nv0.y);
        __half2 h1 = __floats2half2_rn(nv0.z, nv0.w);
        __half2 h2 = __floats2half2_rn(nv1.x, nv1.y);
        __half2 h3 = __floats2half2_rn(nv1.z, nv1.w);
        uint4 ue_;
        ue_.x = *(unsigned*)&h0; ue_.y = *(unsigned*)&h1;
        ue_.z = *(unsigned*)&h2; ue_.w = *(unsigned*)&h3;
        ((uint4*)(nxtH + n * D))[q8] = ue_;
    }
}

// ---------------------------------------------------------------------------
extern "C" void kernel_launch(void* const* d_in, const int* in_sizes, int n_in,
                              void* d_out, int out_size) {
    const float* ue = (const float*)d_in[0];
    const float* ie = (const float*)d_in[1];
    const float* uW = (const float*)d_in[2];
    const float* iW = (const float*)d_in[3];
    const int*   h  = (const int*)d_in[4];
    const int*   t  = (const int*)d_in[5];
    float* out = (float*)d_out;

    const int TB = 256;
    const int n4   = NN * D / 4;
    const int gN4  = (n4 + TB - 1) / TB;
    const int gNN  = (NN + TB - 1) / TB;
    const int gE   = (NE + TB - 1) / TB;
    const int gNW  = (NN * 32 + TB - 1) / TB;   // warp-per-node

    float *embA, *embB;
    __half *embHA, *embHB;
    cudaGetSymbolAddress((void**)&embA, d_embA);
    cudaGetSymbolAddress((void**)&embB, d_embB);
    cudaGetSymbolAddress((void**)&embHA, d_embHA);
    cudaGetSymbolAddress((void**)&embHB, d_embHB);

    k_init<<<gN4, TB>>>(ue, ie, out);
    k_cnt_zero<<<gNN, TB>>>();
    k_cnt<<<gE, TB>>>(h);
    k_blocksum<<<NBLK, SCAN_TB>>>();
    k_scanblk<<<1, 1024>>>();
    k_rowptr<<<NBLK, SCAN_TB>>>();
    k_csr<<<gE, TB>>>(h, t);
    k_scale0<<<gN4, TB>>>();

    float* cur = embA;  float* nxt = embB;
    __half* curH = embHA; __half* nxtH = embHB;
    for (int layer = 0; layer < NL; layer++) {
        k_spmm_gnn<<<gNW, TB>>>();
        k_intent<<<NN / 8, TB>>>(cur, uW, iW);
        k_adaptive<<<gNW, TB>>>(cur, curH, nxt, nxtH, out);
        float* tf = cur; cur = nxt; nxt = tf;
        __half* th = curH; curH = nxtH; nxtH = th;
    }
}